// round 3
// baseline (speedup 1.0000x reference)
#include <cuda_runtime.h>

// LIIF_3d: fused SIREN-MLP decoder, fp32 FFMA baseline.
// Kernel 1: per-64-query block — gather 3x3 neighborhood, 5-layer MLP, write pat.
// Kernel 2: fold3 (9-tap gather) -> output [B,3,H,W].

#define TQ   64      // queries per block
#define KT   32      // K tile
#define D    256     // hidden dim
#define HH   256
#define WWI  256
#define QN   65536   // H*W
#define CIN  64
#define W0F  30.0f

// pat scratch: [B][q][27]
__device__ float g_pat[2 * QN * 27];

__global__ __launch_bounds__(256, 2)
void mlp_kernel(const float* __restrict__ feat, const float* __restrict__ coord,
                const float* __restrict__ w0, const float* __restrict__ b0,
                const float* __restrict__ w1, const float* __restrict__ b1,
                const float* __restrict__ w2, const float* __restrict__ b2,
                const float* __restrict__ w3, const float* __restrict__ b3,
                const float* __restrict__ w4, const float* __restrict__ b4)
{
    extern __shared__ float smem[];
    float* hbuf = smem;                 // TQ*D   = 16384 floats (warp-private rows)
    float* wt   = hbuf + TQ * D;        // KT*D   =  8192 floats (also holds w4: 256*27=6912)
    float* xt   = wt + KT * D;          // TQ*KT  =  2048 floats (layer-0 gathered input)
    int*   qy   = (int*)(xt + TQ * KT); // TQ
    int*   qx   = qy + TQ;              // TQ
    float* tv   = (float*)(qx + TQ);    // TQ

    const int tid  = threadIdx.x;
    const int lane = tid & 31;
    const int wrp  = tid >> 5;
    const int qbase = blockIdx.x * TQ;       // global query id base (B*QN total)
    const int bimg  = qbase >> 16;           // batch index (TQ divides QN)

    // ---- per-query coords ----
    if (tid < TQ) {
        int qg = qbase + tid;
        int q  = qg & (QN - 1);
        const float* cp = coord + (bimg * QN + q) * 3;
        float cy = cp[0], cx = cp[1];
        const float e = 1e-6f;
        cy = fminf(fmaxf(cy, -1.0f + e), 1.0f - e);
        cx = fminf(fmaxf(cx, -1.0f + e), 1.0f - e);
        int iy = (int)rintf((cy + 1.0f) * (HH * 0.5f) - 0.5f);   // rint = half-to-even, matches jnp.round
        int ix = (int)rintf((cx + 1.0f) * (WWI * 0.5f) - 0.5f);
        qy[tid] = min(max(iy, 0), HH - 1);
        qx[tid] = min(max(ix, 0), WWI - 1);
        tv[tid] = cp[2];
    }
    __syncthreads();

    float acc[8][8];
    #pragma unroll
    for (int i = 0; i < 8; i++)
        #pragma unroll
        for (int j = 0; j < 8; j++) acc[i][j] = 0.0f;

    // ================= layer 0: K = 577 (gathered) =================
    for (int kt0 = 0; kt0 < 577; kt0 += KT) {
        int kte = min(KT, 577 - kt0);
        __syncthreads();   // protect wt/xt from previous tile's readers
        {   // stage weight tile w0[kt0..kt0+kte) x 256
            const float4* src = (const float4*)(w0 + kt0 * D);
            float4* dst = (float4*)wt;
            int tot = kte * (D / 4);
            for (int i = tid; i < tot; i += 256) dst[i] = src[i];
        }
        // gather x tile: x[q][k] = feat 3x3 neighborhood (zero-padded), x[576] = t
        for (int i = tid; i < TQ * KT; i += 256) {
            int kk = i & (KT - 1);
            int q  = i >> 5;
            float v = 0.0f;
            if (kk < kte) {
                int k = kt0 + kk;
                if (k == 576) {
                    v = tv[q];
                } else {
                    int c = k / 9;
                    int r = k - c * 9;
                    int di = r / 3;
                    int dj = r - di * 3;
                    int yy = qy[q] + di - 1;
                    int xx = qx[q] + dj - 1;
                    if (yy >= 0 && yy < HH && xx >= 0 && xx < WWI)
                        v = feat[((bimg * CIN + c) * HH + yy) * WWI + xx];
                }
            }
            xt[i] = v;
        }
        __syncthreads();
        #pragma unroll 4
        for (int kk = 0; kk < kte; kk++) {
            float a[8], bb[8];
            #pragma unroll
            for (int qq = 0; qq < 8; qq++) a[qq] = xt[(wrp * 8 + qq) * KT + kk];      // broadcast
            #pragma unroll
            for (int oo = 0; oo < 8; oo++) bb[oo] = wt[kk * D + lane + oo * 32];      // conflict-free
            #pragma unroll
            for (int qq = 0; qq < 8; qq++)
                #pragma unroll
                for (int oo = 0; oo < 8; oo++)
                    acc[qq][oo] = fmaf(a[qq], bb[oo], acc[qq][oo]);
        }
    }
    {   // bias + sin -> hbuf (warp-private rows)
        float bo[8];
        #pragma unroll
        for (int oo = 0; oo < 8; oo++) bo[oo] = b0[lane + oo * 32];
        __syncwarp();
        #pragma unroll
        for (int qq = 0; qq < 8; qq++)
            #pragma unroll
            for (int oo = 0; oo < 8; oo++)
                hbuf[(wrp * 8 + qq) * D + lane + oo * 32] =
                    __sinf(W0F * (acc[qq][oo] + bo[oo]));
    }

    // ================= layers 1..3: 256 -> 256 =================
    const float* Ws[3] = {w1, w2, w3};
    const float* Bs[3] = {b1, b2, b3};
    for (int l = 0; l < 3; l++) {
        #pragma unroll
        for (int i = 0; i < 8; i++)
            #pragma unroll
            for (int j = 0; j < 8; j++) acc[i][j] = 0.0f;
        const float* wl = Ws[l];
        for (int kt0 = 0; kt0 < D; kt0 += KT) {
            __syncthreads();
            {
                const float4* src = (const float4*)(wl + kt0 * D);
                float4* dst = (float4*)wt;
                for (int i = tid; i < KT * (D / 4); i += 256) dst[i] = src[i];
            }
            __syncthreads();
            #pragma unroll 8
            for (int kk = 0; kk < KT; kk++) {
                float a[8], bb[8];
                #pragma unroll
                for (int qq = 0; qq < 8; qq++) a[qq] = hbuf[(wrp * 8 + qq) * D + kt0 + kk];
                #pragma unroll
                for (int oo = 0; oo < 8; oo++) bb[oo] = wt[kk * D + lane + oo * 32];
                #pragma unroll
                for (int qq = 0; qq < 8; qq++)
                    #pragma unroll
                    for (int oo = 0; oo < 8; oo++)
                        acc[qq][oo] = fmaf(a[qq], bb[oo], acc[qq][oo]);
            }
        }
        float bo[8];
        #pragma unroll
        for (int oo = 0; oo < 8; oo++) bo[oo] = Bs[l][lane + oo * 32];
        __syncwarp();   // all lanes of warp done reading hbuf rows before overwrite
        #pragma unroll
        for (int qq = 0; qq < 8; qq++)
            #pragma unroll
            for (int oo = 0; oo < 8; oo++)
                hbuf[(wrp * 8 + qq) * D + lane + oo * 32] =
                    __sinf(W0F * (acc[qq][oo] + bo[oo]));
    }

    // ================= layer 4: 256 -> 27 =================
    __syncthreads();
    for (int i = tid; i < D * 27; i += 256) wt[i] = w4[i];
    __syncthreads();
    if (lane < 27) {
        float b4v = b4[lane];
        float a4[8];
        #pragma unroll
        for (int qq = 0; qq < 8; qq++) a4[qq] = 0.0f;
        for (int k = 0; k < D; k++) {
            float bb = wt[k * 27 + lane];
            #pragma unroll
            for (int qq = 0; qq < 8; qq++)
                a4[qq] = fmaf(hbuf[(wrp * 8 + qq) * D + k], bb, a4[qq]);
        }
        #pragma unroll
        for (int qq = 0; qq < 8; qq++) {
            int qg = qbase + wrp * 8 + qq;
            g_pat[qg * 27 + lane] = a4[qq] + b4v;
        }
    }
}

// fold3: out[b,c,y,x] = sum_{i,j} pat[b, (y+1-i)*W + (x+1-j), c*9 + i*3 + j]
__global__ void fold_kernel(float* __restrict__ out)
{
    int idx = blockIdx.x * blockDim.x + threadIdx.x;   // over B*H*W = 131072
    if (idx >= 2 * QN) return;
    int b = idx >> 16;
    int p = idx & (QN - 1);
    int y = p >> 8, x = p & 255;
    float s0 = 0.f, s1 = 0.f, s2 = 0.f;
    #pragma unroll
    for (int i = 0; i < 3; i++) {
        int yy = y + 1 - i;
        if (yy < 0 || yy >= HH) continue;
        #pragma unroll
        for (int j = 0; j < 3; j++) {
            int xx = x + 1 - j;
            if (xx < 0 || xx >= WWI) continue;
            const float* pp = g_pat + (b * QN + yy * WWI + xx) * 27 + i * 3 + j;
            s0 += pp[0];
            s1 += pp[9];
            s2 += pp[18];
        }
    }
    out[(b * 3 + 0) * QN + p] = s0;
    out[(b * 3 + 1) * QN + p] = s1;
    out[(b * 3 + 2) * QN + p] = s2;
}

extern "C" void kernel_launch(void* const* d_in, const int* in_sizes, int n_in,
                              void* d_out, int out_size)
{
    const float* feat  = (const float*)d_in[0];
    const float* coord = (const float*)d_in[1];
    const float* w0 = (const float*)d_in[2];
    const float* b0 = (const float*)d_in[3];
    const float* w1 = (const float*)d_in[4];
    const float* b1 = (const float*)d_in[5];
    const float* w2 = (const float*)d_in[6];
    const float* b2 = (const float*)d_in[7];
    const float* w3 = (const float*)d_in[8];
    const float* b3 = (const float*)d_in[9];
    const float* w4 = (const float*)d_in[10];
    const float* b4 = (const float*)d_in[11];
    float* out = (float*)d_out;

    const int smem_bytes = (TQ * D + KT * D + TQ * KT) * 4 + TQ * 12;  // 107264
    cudaFuncSetAttribute(mlp_kernel, cudaFuncAttributeMaxDynamicSharedMemorySize, smem_bytes);

    mlp_kernel<<<(2 * QN) / TQ, 256, smem_bytes>>>(feat, coord,
                                                   w0, b0, w1, b1, w2, b2, w3, b3, w4, b4);
    fold_kernel<<<(2 * QN + 255) / 256, 256>>>(out);
}

// round 5
// speedup vs baseline: 2.1100x; 2.1100x over previous
#include <cuda_runtime.h>
#include <cuda_fp16.h>
#include <cstdint>

// ============================================================
// LIIF_3d via HMMA (mma.sync m16n8k16 fp16, f32 accum, hi/lo 3-split).
//   prep_kernel : transpose + fp16 hi/lo split of weights
//   mlp_hmma    : 1 CTA = 128 queries; gather + 5-layer SIREN MLP -> g_pat
//   fold_kernel : 9-tap gather fold -> output [B,3,H,W]
// ============================================================

#define HH   256
#define WWI  256
#define QN   65536
#define CIN  64
#define W0F  30.0f
#define MQ   128
#define SA   264           // A row stride in halfs (256 + 8 pad -> conflict-free ldmatrix)
#define SB   72            // B row stride in halfs (64 + 8 pad)

#define SM_COORD 0                      // qy[128] qx[128] tv[128] = 1536B
#define SM_AHI   2048
#define SM_ALO   (SM_AHI + 128 * SA * 2)   // 69632
#define SM_BHI   (SM_ALO + 128 * SA * 2)   // 137216
#define SM_BLO   (SM_BHI + 256 * SB * 2)   // 174080
#define SM_TOTAL (SM_BLO + 256 * SB * 2)   // 210944

// transposed split weights, [n][kp] row-major per segment:
//  L0: 256x640 (k>=577 zero, k==576 = t column); L1-3: 256x256; L4: 64x256 (n>=27 zero)
#define WT_ELEMS 376832
__device__ __half g_wt_hi[WT_ELEMS];
__device__ __half g_wt_lo[WT_ELEMS];
__device__ float  g_pat[2 * QN * 27];

static __device__ __forceinline__ uint32_t smem_u32(const void* p) {
    uint32_t a;
    asm("{ .reg .u64 t; cvta.to.shared.u64 t, %1; cvt.u32.u64 %0, t; }" : "=r"(a) : "l"(p));
    return a;
}

#define LDSM4(r, addr)                                                              \
    asm volatile("ldmatrix.sync.aligned.m8n8.x4.shared.b16 {%0,%1,%2,%3}, [%4];"    \
                 : "=r"((r)[0]), "=r"((r)[1]), "=r"((r)[2]), "=r"((r)[3])           \
                 : "r"(addr) : "memory")

static __device__ __forceinline__ void mma16816(float* c, const uint32_t* a, const uint32_t* b) {
    asm volatile(
        "mma.sync.aligned.m16n8k16.row.col.f32.f16.f16.f32 "
        "{%0,%1,%2,%3}, {%4,%5,%6,%7}, {%8,%9}, {%0,%1,%2,%3};"
        : "+f"(c[0]), "+f"(c[1]), "+f"(c[2]), "+f"(c[3])
        : "r"(a[0]), "r"(a[1]), "r"(a[2]), "r"(a[3]), "r"(b[0]), "r"(b[1]));
}

// ---------------- prep: transpose + hi/lo split ----------------
__global__ void prep_kernel(const float* __restrict__ w0, const float* __restrict__ w1,
                            const float* __restrict__ w2, const float* __restrict__ w3,
                            const float* __restrict__ w4) {
    int i = blockIdx.x * 256 + threadIdx.x;
    if (i >= WT_ELEMS) return;
    float v;
    if (i < 163840) {                 // L0 [256][640]
        int n = i / 640, k = i - n * 640;
        v = (k < 577) ? w0[k * 256 + n] : 0.0f;
    } else if (i < 229376) {
        int j = i - 163840; int n = j >> 8, k = j & 255; v = w1[k * 256 + n];
    } else if (i < 294912) {
        int j = i - 229376; int n = j >> 8, k = j & 255; v = w2[k * 256 + n];
    } else if (i < 360448) {
        int j = i - 294912; int n = j >> 8, k = j & 255; v = w3[k * 256 + n];
    } else {                          // L4 [64][256], rows >=27 zero
        int j = i - 360448; int n = j >> 8, k = j & 255;
        v = (n < 27) ? w4[k * 27 + n] : 0.0f;
    }
    __half h = __float2half_rn(v);
    g_wt_hi[i] = h;
    g_wt_lo[i] = __float2half_rn(v - __half2float(h));
}

// ---------------- fused MLP ----------------
__global__ __launch_bounds__(512, 1)
void mlp_hmma(const float* __restrict__ feat, const float* __restrict__ coord,
              const float* __restrict__ b0, const float* __restrict__ b1,
              const float* __restrict__ b2, const float* __restrict__ b3,
              const float* __restrict__ b4) {
    extern __shared__ char smem[];
    const uint32_t sb = smem_u32(smem);
    int*   qy = (int*)(smem + SM_COORD);
    int*   qx = qy + MQ;
    float* tv = (float*)(qx + MQ);

    const int tid  = threadIdx.x;
    const int lane = tid & 31;
    const int w    = tid >> 5;
    const int wm   = w >> 2;           // 0..3  (M groups of 32 rows)
    const int wn   = w & 3;            // 0..3  (N groups of 64 cols)
    const int qbase = blockIdx.x * MQ;
    const int bimg  = qbase >> 16;

    if (tid < MQ) {
        int qg = qbase + tid;
        int q  = qg & (QN - 1);
        const float* cp = coord + (bimg * QN + q) * 3;
        float cy = cp[0], cx = cp[1];
        const float e = 1e-6f;
        cy = fminf(fmaxf(cy, -1.0f + e), 1.0f - e);
        cx = fminf(fmaxf(cx, -1.0f + e), 1.0f - e);
        int iy = (int)rintf((cy + 1.0f) * (HH * 0.5f) - 0.5f);
        int ix = (int)rintf((cx + 1.0f) * (WWI * 0.5f) - 0.5f);
        qy[tid] = min(max(iy, 0), HH - 1);
        qx[tid] = min(max(ix, 0), WWI - 1);
        tv[tid] = cp[2];
    }
    __syncthreads();

    const float* Bias[4] = {b0, b1, b2, b3};
    const int seg[5] = {0, 163840, 229376, 294912, 360448};
    const int kps[5] = {640, 256, 256, 256, 256};

    const int rowbase = wm * 32;
    // ldmatrix lane addressing (see fragment layouts): conflict-free via +8-half row pad
    const uint32_t a_off = (uint32_t)(((rowbase + (lane & 15)) * SA + ((lane >> 4) << 3)) * 2);
    const uint32_t aHi = sb + SM_AHI + a_off;
    const uint32_t aLo = sb + SM_ALO + a_off;
    const uint32_t b_off = (uint32_t)(((wn * 64 + ((lane >> 4) << 3) + (lane & 7)) * SB +
                                      ((lane >> 3) & 1) * 8) * 2);
    const uint32_t bHi = sb + SM_BHI + b_off;
    const uint32_t bLo = sb + SM_BLO + b_off;

    float acc[2][8][4];

    for (int l = 0; l < 5; l++) {
        #pragma unroll
        for (int mt = 0; mt < 2; mt++)
            #pragma unroll
            for (int nt = 0; nt < 8; nt++)
                #pragma unroll
                for (int i = 0; i < 4; i++) acc[mt][nt][i] = 0.0f;

        const int kp = kps[l];
        const int nrows = (l == 4) ? 64 : 256;
        const int nstages = (l == 0) ? 3 : 1;

        for (int s = 0; s < nstages; s++) {
            const int klen = (l == 0) ? ((s < 2) ? 256 : 128) : 256;
            __syncthreads();                        // A region free (all prior reads done)
            if (l == 0) {
                // gather stage: cols j -> global k = s*256 + j; lanes span q => coalesced
                for (int idx = tid; idx < MQ * klen; idx += 512) {
                    int q = idx & (MQ - 1);
                    int j = idx >> 7;
                    int k = s * 256 + j;
                    float v = 0.0f;
                    if (k < 576) {
                        int ci = k / 9, r9 = k - ci * 9;
                        int di = r9 / 3, dj = r9 - di * 3;
                        int yy = qy[q] + di - 1, xx = qx[q] + dj - 1;
                        if (yy >= 0 && yy < HH && xx >= 0 && xx < WWI)
                            v = __ldg(feat + ((bimg * CIN + ci) * HH + yy) * WWI + xx);
                    } else if (k == 576) {
                        v = tv[q];
                    }
                    __half h  = __float2half_rn(v);
                    __half lo = __float2half_rn(v - __half2float(h));
                    uint32_t off = (uint32_t)((q * SA + j) * 2);
                    *(__half*)(smem + SM_AHI + off) = h;
                    *(__half*)(smem + SM_ALO + off) = lo;
                }
            }
            const int nch = klen >> 6;
            for (int c = 0; c < nch; c++) {
                const int kg = s * 256 + c * 64;
                __syncthreads();                    // B buffer free
                // stage B chunk [nrows][64] hi/lo (coalesced LDG, padded STS)
                for (int idx = tid; idx < nrows * 8; idx += 512) {
                    int n = idx >> 3, u = idx & 7;
                    uint32_t soff = (uint32_t)((n * SB + u * 8) * 2);
                    const __half* ph = g_wt_hi + seg[l] + n * kp + kg + u * 8;
                    const __half* pl = g_wt_lo + seg[l] + n * kp + kg + u * 8;
                    *(uint4*)(smem + SM_BHI + soff) = *(const uint4*)ph;
                    *(uint4*)(smem + SM_BLO + soff) = *(const uint4*)pl;
                }
                __syncthreads();
                if (l < 4 || wn == 0) {
                    #pragma unroll
                    for (int ks = 0; ks < 4; ks++) {
                        const uint32_t ca2 = (uint32_t)((c * 64 + ks * 16) * 2);
                        uint32_t Ah[8], Al[8], Bh[16], Bl[16];
                        LDSM4(Ah,     aHi + ca2);
                        LDSM4(Ah + 4, aHi + ca2 + 16 * SA * 2);
                        LDSM4(Al,     aLo + ca2);
                        LDSM4(Al + 4, aLo + ca2 + 16 * SA * 2);
                        #pragma unroll
                        for (int p = 0; p < 4; p++)
                            LDSM4(Bh + 4 * p, bHi + (uint32_t)(p * 16 * SB * 2 + ks * 32));
                        #pragma unroll
                        for (int mt = 0; mt < 2; mt++)
                            #pragma unroll
                            for (int nt = 0; nt < 8; nt++)
                                mma16816(acc[mt][nt], Ah + 4 * mt, Bh + 2 * nt);
                        #pragma unroll
                        for (int mt = 0; mt < 2; mt++)
                            #pragma unroll
                            for (int nt = 0; nt < 8; nt++)
                                mma16816(acc[mt][nt], Al + 4 * mt, Bh + 2 * nt);
                        #pragma unroll
                        for (int p = 0; p < 4; p++)
                            LDSM4(Bl + 4 * p, bLo + (uint32_t)(p * 16 * SB * 2 + ks * 32));
                        #pragma unroll
                        for (int mt = 0; mt < 2; mt++)
                            #pragma unroll
                            for (int nt = 0; nt < 8; nt++)
                                mma16816(acc[mt][nt], Ah + 4 * mt, Bl + 2 * nt);
                    }
                }
            }
        }

        __syncthreads();   // all warps done reading A before epilogue overwrites it
        if (l < 4) {
            const float* bp = Bias[l];
            const int trow  = rowbase + (lane >> 2);
            const int tcol0 = wn * 64 + 2 * (lane & 3);
            #pragma unroll
            for (int mt = 0; mt < 2; mt++) {
                #pragma unroll
                for (int nt = 0; nt < 8; nt++) {
                    int col = tcol0 + nt * 8;
                    float2 bb = *(const float2*)(bp + col);
                    int r0 = trow + mt * 16;
                    int r1 = r0 + 8;
                    float v00 = __sinf(W0F * (acc[mt][nt][0] + bb.x));
                    float v01 = __sinf(W0F * (acc[mt][nt][1] + bb.y));
                    float v10 = __sinf(W0F * (acc[mt][nt][2] + bb.x));
                    float v11 = __sinf(W0F * (acc[mt][nt][3] + bb.y));
                    __half h00 = __float2half_rn(v00), h01 = __float2half_rn(v01);
                    __half h10 = __float2half_rn(v10), h11 = __float2half_rn(v11);
                    __half l00 = __float2half_rn(v00 - __half2float(h00));
                    __half l01 = __float2half_rn(v01 - __half2float(h01));
                    __half l10 = __float2half_rn(v10 - __half2float(h10));
                    __half l11 = __float2half_rn(v11 - __half2float(h11));
                    uint32_t o0 = (uint32_t)((r0 * SA + col) * 2);
                    uint32_t o1 = (uint32_t)((r1 * SA + col) * 2);
                    *(__half2*)(smem + SM_AHI + o0) = __halves2half2(h00, h01);
                    *(__half2*)(smem + SM_ALO + o0) = __halves2half2(l00, l01);
                    *(__half2*)(smem + SM_AHI + o1) = __halves2half2(h10, h11);
                    *(__half2*)(smem + SM_ALO + o1) = __halves2half2(l10, l11);
                }
            }
        } else if (wn == 0) {
            const int trow  = rowbase + (lane >> 2);
            const int tcol0 = 2 * (lane & 3);
            #pragma unroll
            for (int mt = 0; mt < 2; mt++) {
                #pragma unroll
                for (int nt = 0; nt < 4; nt++) {      // cols 0..31; only <27 valid
                    int col = tcol0 + nt * 8;
                    int r0 = trow + mt * 16;
                    int qg0 = qbase + r0;
                    int qg1 = qg0 + 8;
                    if (col < 27) {
                        float bv = __ldg(b4 + col);
                        g_pat[qg0 * 27 + col] = acc[mt][nt][0] + bv;
                        g_pat[qg1 * 27 + col] = acc[mt][nt][2] + bv;
                    }
                    if (col + 1 < 27) {
                        float bv = __ldg(b4 + col + 1);
                        g_pat[qg0 * 27 + col + 1] = acc[mt][nt][1] + bv;
                        g_pat[qg1 * 27 + col + 1] = acc[mt][nt][3] + bv;
                    }
                }
            }
        }
    }
}

// ---------------- fold3 ----------------
__global__ void fold_kernel(float* __restrict__ out) {
    int idx = blockIdx.x * blockDim.x + threadIdx.x;
    if (idx >= 2 * QN) return;
    int b = idx >> 16;
    int p = idx & (QN - 1);
    int y = p >> 8, x = p & 255;
    float s0 = 0.f, s1 = 0.f, s2 = 0.f;
    #pragma unroll
    for (int i = 0; i < 3; i++) {
        int yy = y + 1 - i;
        if (yy < 0 || yy >= HH) continue;
        #pragma unroll
        for (int j = 0; j < 3; j++) {
            int xx = x + 1 - j;
            if (xx < 0 || xx >= WWI) continue;
            const float* pp = g_pat + (b * QN + yy * WWI + xx) * 27 + i * 3 + j;
            s0 += pp[0];
            s1 += pp[9];
            s2 += pp[18];
        }
    }
    out[(b * 3 + 0) * QN + p] = s0;
    out[(b * 3 + 1) * QN + p] = s1;
    out[(b * 3 + 2) * QN + p] = s2;
}

extern "C" void kernel_launch(void* const* d_in, const int* in_sizes, int n_in,
                              void* d_out, int out_size) {
    const float* feat  = (const float*)d_in[0];
    const float* coord = (const float*)d_in[1];
    const float* w0 = (const float*)d_in[2];
    const float* b0 = (const float*)d_in[3];
    const float* w1 = (const float*)d_in[4];
    const float* b1 = (const float*)d_in[5];
    const float* w2 = (const float*)d_in[6];
    const float* b2 = (const float*)d_in[7];
    const float* w3 = (const float*)d_in[8];
    const float* b3 = (const float*)d_in[9];
    const float* w4 = (const float*)d_in[10];
    const float* b4 = (const float*)d_in[11];
    float* out = (float*)d_out;

    prep_kernel<<<(WT_ELEMS + 255) / 256, 256>>>(w0, w1, w2, w3, w4);

    cudaFuncSetAttribute(mlp_hmma, cudaFuncAttributeMaxDynamicSharedMemorySize, SM_TOTAL);
    mlp_hmma<<<(2 * QN) / MQ, 512, SM_TOTAL>>>(feat, coord, b0, b1, b2, b3, b4);

    fold_kernel<<<(2 * QN + 255) / 256, 256>>>(out);
}